// round 15
// baseline (speedup 1.0000x reference)
#include <cuda_runtime.h>
#include <cstdint>

// R15 = R14 body with BLOCK=256 (grid=512, ~27.7 warps/SM vs 21 at BLOCK=128).
// __launch_bounds__(256,4): single wave (4*148=592 >= 512), smem 100KB/SM.
// Init M-GEMM redistributed over 256 threads (same per-acc chains -> same bits).
// Per-batch math byte-identical to R14. rel_err must stay 0.0009249507.
// Output layout: [recon (nb*8)] [lat (nb*16)] [A (nb*64)]

constexpr int NN = 8;
constexpr int BLOCK = 256;

using u64 = unsigned long long;

__device__ __forceinline__ u64 pk(float lo, float hi) {
    u64 r; asm("mov.b64 %0, {%1,%2};" : "=l"(r) : "f"(lo), "f"(hi)); return r;
}
__device__ __forceinline__ void upk(u64 v, float& lo, float& hi) {
    asm("mov.b64 {%0,%1}, %2;" : "=f"(lo), "=f"(hi) : "l"(v));
}
__device__ __forceinline__ u64 fma2(u64 a, u64 b, u64 c) {
    u64 d; asm("fma.rn.f32x2 %0, %1, %2, %3;" : "=l"(d) : "l"(a), "l"(b), "l"(c)); return d;
}
__device__ __forceinline__ u64 add2(u64 a, u64 b) {
    u64 d; asm("add.rn.f32x2 %0, %1, %2;" : "=l"(d) : "l"(a), "l"(b)); return d;
}
__device__ __forceinline__ u64 dup2(float v) { return pk(v, v); }
__device__ __forceinline__ u64 relu2(u64 v) {
    float a, b; upk(v, a, b);
    return pk(fmaxf(a, 0.0f), fmaxf(b, 0.0f));
}
__device__ __forceinline__ u64 shflx_u64(u64 v, int m) {
    float lo, hi; upk(v, lo, hi);
    lo = __shfl_xor_sync(0xffffffffu, lo, m);
    hi = __shfl_xor_sync(0xffffffffu, hi, m);
    return pk(lo, hi);
}

__device__ __forceinline__ constexpr int PIDX(int i, int j) { // i<j, 0..27
    return i * 7 - (i * (i - 1)) / 2 + (j - i - 1);
}

__global__ void __launch_bounds__(BLOCK, 4)
gae_kernel(const float* __restrict__ x, const float* __restrict__ noise,
           const float* __restrict__ We1, const float* __restrict__ be1,
           const float* __restrict__ We2, const float* __restrict__ be2,
           const float* __restrict__ Wg1, const float* __restrict__ bg1,
           const float* __restrict__ Wg2, const float* __restrict__ bg2,
           const float* __restrict__ Wd1, const float* __restrict__ bd1,
           const float* __restrict__ Wd2, const float* __restrict__ bd2,
           float* __restrict__ out, int nb)
{
    __shared__ float4 sencWq[64];       // (w1,w1, e0,e0)
    __shared__ float2 sencE1[64];       // (e1,e1)
    __shared__ float4 sencC[128];       // [k][2]: c_i = fmaf(i, w2, be1)
    __shared__ float4 sWg1q[32];        // (g0,g0, g1,g1)
    __shared__ float2 sWg1b[32];        // (bg,bg)
    __shared__ float4 sMT4[64 * 8];     // fused decoder M[e][c], c contiguous
    __shared__ float2 scw[64];          // (bg2@Wd1 + bd1, Wd2[e][1])
    __shared__ float  sbd2v;
    __shared__ float  sWg2T[32 * 33];   // Wg2 transposed, padded (staging)
    __shared__ float4 sWd1s4[32 * 16];  // Wd1 staged: [d][pp]

    const int t = threadIdx.x;
    const u64 z2 = pk(0.0f, 0.0f);

    // ---- stage raw weights ----
    if (t < 64) {
        float w1 = We1[64 + t];
        float w2 = We1[128 + t];
        float be = be1[t];
        float e0 = We2[2 * t], e1 = We2[2 * t + 1];
        sencWq[t] = make_float4(w1, w1, e0, e0);
        sencE1[t] = make_float2(e1, e1);
        float c[8];
        #pragma unroll
        for (int i = 0; i < 8; i++) c[i] = fmaf((float)i, w2, be);
        sencC[2 * t]     = make_float4(c[0], c[1], c[2], c[3]);
        sencC[2 * t + 1] = make_float4(c[4], c[5], c[6], c[7]);
    }
    if (t < 32) {
        float g0 = Wg1[t], g1 = Wg1[32 + t], bg = bg1[t];
        sWg1q[t] = make_float4(g0, g0, g1, g1);
        sWg1b[t] = make_float2(bg, bg);
    }
    for (int idx = t; idx < 1024; idx += BLOCK) {
        int c = idx >> 5, d = idx & 31;
        sWg2T[d * 33 + c] = Wg2[idx];
    }
    for (int idx = t; idx < 512; idx += BLOCK) {
        sWd1s4[idx] = *(const float4*)&Wd1[4 * idx];
    }
    if (t == 0) sbd2v = bd2[1];
    __syncthreads();

    // ---- fused decoder weights: M[e][c] = sum_d Wg2[c][d]*Wd1[d][e] ----
    // 256 threads: column c = t&31, e-pair group ep0 = t>>5 in 0..7 (4 pairs each).
    // Per-accumulator d-ordered fma2 chains identical to prior rounds.
    {
        int c = t & 31, ep0 = t >> 5;
        u64 acc[4];
        #pragma unroll
        for (int k = 0; k < 4; k++) acc[k] = z2;
        #pragma unroll 2
        for (int d = 0; d < 32; d++) {
            u64 ad = dup2(sWg2T[d * 33 + c]);
            const ulonglong2* fb = (const ulonglong2*)&sWd1s4[d * 16 + ep0 * 2];
            ulonglong2 v0 = fb[0], v1 = fb[1];
            acc[0] = fma2(ad, v0.x, acc[0]);
            acc[1] = fma2(ad, v0.y, acc[1]);
            acc[2] = fma2(ad, v1.x, acc[2]);
            acc[3] = fma2(ad, v1.y, acc[3]);
        }
        #pragma unroll
        for (int k = 0; k < 4; k++) {
            int p = ep0 * 4 + k;
            float mlo, mhi; upk(acc[k], mlo, mhi);
            ((float*)sMT4)[(2 * p)     * 32 + c] = mlo;
            ((float*)sMT4)[(2 * p + 1) * 32 + c] = mhi;
        }
    }
    if (t < 64) {
        float ce = bd1[t];
        int pp = t >> 2, r = t & 3;
        #pragma unroll
        for (int d = 0; d < 32; d++) {
            float4 w = sWd1s4[d * 16 + pp];
            float vv = (r & 2) ? ((r & 1) ? w.w : w.z) : ((r & 1) ? w.y : w.x);
            ce = fmaf(bg2[d], vv, ce);
        }
        scw[t] = make_float2(ce, Wd2[t * 3 + 1]);
    }
    __syncthreads();

    const int b = blockIdx.x * BLOCK + t;
    if (b >= nb) return;

    float* out_recon = out;
    float* out_lat   = out + (size_t)nb * 8;
    float* out_A     = out + (size_t)nb * 24;

    // ---------------- P0: load x directly as 64-bit pairs ----------------
    u64 x2[4];
    {
        const ulonglong2* xp = (const ulonglong2*)(x + (size_t)b * 8);
        ulonglong2 xa = xp[0], xb = xp[1];
        x2[0] = xa.x; x2[1] = xa.y; x2[2] = xb.x; x2[3] = xb.y;
    }

    // ---------------- P1: encoder ----------------
    u64 l0p[4], l1p[4];
    #pragma unroll
    for (int q = 0; q < 4; q++) { l0p[q] = z2; l1p[q] = z2; }

    #pragma unroll 2
    for (int k = 0; k < 64; k++) {
        ulonglong2 wv = *(const ulonglong2*)&sencWq[k];
        u64 w1d = wv.x, e0d = wv.y;
        u64 e1d = ((const u64*)sencE1)[k];
        const ulonglong2* cc = (const ulonglong2*)&sencC[2 * k];
        ulonglong2 c01 = cc[0], c23 = cc[1];
        u64 c2[4] = { c01.x, c01.y, c23.x, c23.y };
        #pragma unroll
        for (int q = 0; q < 4; q++) {
            u64 h = relu2(fma2(x2[q], w1d, c2[q]));
            l0p[q] = fma2(h, e0d, l0p[q]);
            l1p[q] = fma2(h, e1d, l1p[q]);
        }
    }

    // ---------------- P2/P3: stats, noise, px/py, lat store ----------------
    float px[8], py[8];
    {
        float l0[8], l1[8];
        #pragma unroll
        for (int q = 0; q < 4; q++) {
            upk(l0p[q], l0[2 * q], l0[2 * q + 1]);
            upk(l1p[q], l1[2 * q], l1[2 * q + 1]);
        }
        float mu0 = 0.0f, mu1 = 0.0f;
        #pragma unroll
        for (int i = 0; i < 8; i++) { mu0 += l0[i]; mu1 += l1[i]; }
        mu0 *= 0.125f; mu1 *= 0.125f;

        float v0 = 0.0f, v1 = 0.0f;
        #pragma unroll
        for (int i = 0; i < 8; i++) {
            float c0 = l0[i] - mu0, c1 = l1[i] - mu1;
            v0 += c0 * c0; v1 += c1 * c1;
        }
        float sc0 = 3.0f / (sqrtf(v0 * (1.0f / 7.0f)) + 1e-8f);
        float sc1 = 3.0f / (sqrtf(v1 * (1.0f / 7.0f)) + 1e-8f);

        float nz[16];
        {
            const float4* np = (const float4*)(noise + (size_t)b * 16);
            float4 q0 = np[0], q1 = np[1], q2 = np[2], q3 = np[3];
            nz[0]=q0.x; nz[1]=q0.y; nz[2]=q0.z; nz[3]=q0.w;
            nz[4]=q1.x; nz[5]=q1.y; nz[6]=q1.z; nz[7]=q1.w;
            nz[8]=q2.x; nz[9]=q2.y; nz[10]=q2.z; nz[11]=q2.w;
            nz[12]=q3.x; nz[13]=q3.y; nz[14]=q3.z; nz[15]=q3.w;
        }
        #pragma unroll
        for (int i = 0; i < 8; i++) {
            px[i] = ((l0[i] - mu0) * sc0) + nz[2 * i]     * 0.05f;
            py[i] = ((l1[i] - mu1) * sc1) + nz[2 * i + 1] * 0.05f;
        }
        float4* lp = (float4*)(out_lat + (size_t)b * 16);
        #pragma unroll
        for (int q = 0; q < 4; q++) {
            float4 o;
            o.x = px[2 * q];     o.y = py[2 * q];
            o.z = px[2 * q + 1]; o.w = py[2 * q + 1];
            lp[q] = o;
        }
    }

    // ---------------- P4: Gabriel graph (expression-identical) ----------------
    unsigned am = 0;
    int deg[8];
    #pragma unroll
    for (int i = 0; i < 8; i++) deg[i] = 1;

    #pragma unroll
    for (int i = 0; i < 8; i++) {
        #pragma unroll
        for (int j = i + 1; j < 8; j++) {
            float mx = (px[i] + px[j]) * 0.5f;
            float my = (py[i] + py[j]) * 0.5f;
            float dx = px[i] - mx, dy = py[i] - my;
            float r2 = dx * dx + dy * dy;
            float mind2 = 3.402823e38f;
            #pragma unroll
            for (int k = 0; k < 8; k++) {
                if (k != i && k != j) {
                    float ax = px[k] - mx, ay = py[k] - my;
                    mind2 = fminf(mind2, ax * ax + ay * ay);
                }
            }
            if (mind2 >= r2) {
                am |= (1u << PIDX(i, j));
                deg[i]++; deg[j]++;
            }
        }
    }

    float dinv[8];
    #pragma unroll
    for (int i = 0; i < 8; i++) dinv[i] = rsqrtf((float)deg[i]);

    // ---------------- A output: warp-coalesced via bitmask shuffle ----------
    {
        const int lane = t & 31;
        const int m_  = lane & 15;
        const int ai_ = m_ >> 1;
        const int jb  = (m_ & 1) * 4;
        int sh[4];
        #pragma unroll
        for (int jj = 0; jj < 4; jj++) {
            int j = jb + jj;
            if (j == ai_) sh[jj] = 31;
            else {
                int lo = ai_ < j ? ai_ : j;
                int hi = ai_ < j ? j : ai_;
                sh[jj] = lo * 7 - (lo * (lo - 1)) / 2 + (hi - lo - 1);
            }
        }
        float4* warpA = (float4*)(out_A + (size_t)(blockIdx.x * BLOCK + (t & ~31)) * 64);
        #pragma unroll
        for (int k = 0; k < 16; k++) {
            unsigned a = __shfl_sync(0xffffffffu, am, 2 * k + (lane >> 4));
            float4 o;
            o.x = ((a >> sh[0]) & 1u) ? 1.0f : 0.0f;
            o.y = ((a >> sh[1]) & 1u) ? 1.0f : 0.0f;
            o.z = ((a >> sh[2]) & 1u) ? 1.0f : 0.0f;
            o.w = ((a >> sh[3]) & 1u) ? 1.0f : 0.0f;
            warpA[k * 32 + lane] = o;
        }
    }

    // ---------------- P5: qx/qy/s via wx = dinv*px (predicated adds) --------
    u64 qx2[4], qy2[4], s2[4];
    {
        float wx[8], wy[8];
        #pragma unroll
        for (int j = 0; j < 8; j++) {
            wx[j] = dinv[j] * px[j];
            wy[j] = dinv[j] * py[j];
        }

        float tqx = 0.0f, tqy = 0.0f, ts = 0.0f;
        #pragma unroll
        for (int n = 0; n < 8; n++) {
            float tx = wx[n], ty = wy[n], td = dinv[n];
            #pragma unroll
            for (int j = 0; j < 8; j++) {
                if (j == n) continue;
                int p = (n < j) ? PIDX(n, j) : PIDX(j, n);
                bool adj = (am >> p) & 1u;
                if (adj) { tx += wx[j]; ty += wy[j]; td += dinv[j]; }
            }
            float qxn = dinv[n] * tx;
            float qyn = dinv[n] * ty;
            float sn  = dinv[n] * td * 0.125f;
            if (n & 1) {
                qx2[n >> 1] = pk(tqx, qxn);
                qy2[n >> 1] = pk(tqy, qyn);
                s2[n >> 1]  = pk(ts, sn);
            } else {
                tqx = qxn; tqy = qyn; ts = sn;
            }
        }
    }

    // ---------------- P6: GCN channel values u_c ----------------
    u64 u2[16];
    {
        float tu = 0.0f;
        #pragma unroll 2
        for (int c = 0; c < 32; c++) {
            ulonglong2 gv = *(const ulonglong2*)&sWg1q[c];
            u64 g0d = gv.x, g1d = gv.y;
            u64 bgd = ((const u64*)sWg1b)[c];
            u64 acc2 = z2;
            #pragma unroll
            for (int q = 0; q < 4; q++) {
                u64 a = fma2(qx2[q], g0d, fma2(qy2[q], g1d, bgd));
                acc2 = fma2(s2[q], relu2(a), acc2);
            }
            float ua, ub; upk(acc2, ua, ub);
            float uc = ua + ub;
            if (c & 1) u2[c >> 1] = pk(tu, uc);
            else       tu = uc;
        }
    }

    // ---------------- P7: pair-split decoder, warp-rotated e order ----------
    float recon = sbd2v;
    {
        const int lane = t & 31;
        const bool lowq = (lane & 16) == 0;
        const int rot = (t >> 5) << 4;               // per-warp rotation

        u64 uo[8], up_[8];
        #pragma unroll
        for (int k = 0; k < 8; k++) {
            uo[k]   = lowq ? u2[k]     : u2[k + 8];
            u64 snd = lowq ? u2[k + 8] : u2[k];
            up_[k]  = shflx_u64(snd, 16);
        }

        const int colbase = lowq ? 0 : 4;
        #pragma unroll 2
        for (int ee = 0; ee < 64; ee++) {
            int e = (ee + rot) & 63;
            const ulonglong2* wr2 = (const ulonglong2*)&sMT4[e * 8 + colbase];
            ulonglong2 v0 = wr2[0], v1 = wr2[1], v2 = wr2[2], v3 = wr2[3];
            u64 m0 = v0.x, m1 = v0.y, m2 = v1.x, m3 = v1.y;
            u64 m4 = v2.x, m5 = v2.y, m6 = v3.x, m7 = v3.y;

            u64 aA = fma2(uo[0], m0, z2); u64 aB = fma2(uo[1], m1, z2);
            aA = fma2(uo[2], m2, aA);     aB = fma2(uo[3], m3, aB);
            aA = fma2(uo[4], m4, aA);     aB = fma2(uo[5], m5, aB);
            aA = fma2(uo[6], m6, aA);     aB = fma2(uo[7], m7, aB);
            u64 ao = add2(aA, aB);
            float oa, ob; upk(ao, oa, ob);
            float p_own = oa + ob;

            u64 bA = fma2(up_[0], m0, z2); u64 bB = fma2(up_[1], m1, z2);
            bA = fma2(up_[2], m2, bA);     bB = fma2(up_[3], m3, bB);
            bA = fma2(up_[4], m4, bA);     bB = fma2(up_[5], m5, bB);
            bA = fma2(up_[6], m6, bA);     bB = fma2(up_[7], m7, bB);
            u64 bo = add2(bA, bB);
            float pa, pb; upk(bo, pa, pb);
            float p_oth = pa + pb;

            float p_rcv = __shfl_xor_sync(0xffffffffu, p_oth, 16);

            float2 cw = scw[e];
            float pre = (p_own + p_rcv) + cw.x;
            recon = fmaf(fmaxf(pre, 0.0f), cw.y, recon);
        }
    }

    {
        float4 r4 = {recon, recon, recon, recon};
        float4* rp = (float4*)(out_recon + (size_t)b * 8);
        rp[0] = r4;
        rp[1] = r4;
    }
}

extern "C" void kernel_launch(void* const* d_in, const int* in_sizes, int n_in,
                              void* d_out, int out_size)
{
    const float* x     = (const float*)d_in[0];
    const float* noise = (const float*)d_in[1];
    const float* We1   = (const float*)d_in[2];
    const float* be1   = (const float*)d_in[3];
    const float* We2   = (const float*)d_in[4];
    const float* be2   = (const float*)d_in[5];
    const float* Wg1   = (const float*)d_in[6];
    const float* bg1   = (const float*)d_in[7];
    const float* Wg2   = (const float*)d_in[8];
    const float* bg2   = (const float*)d_in[9];
    const float* Wd1   = (const float*)d_in[10];
    const float* bd1   = (const float*)d_in[11];
    const float* Wd2   = (const float*)d_in[12];
    const float* bd2   = (const float*)d_in[13];

    const int nb = in_sizes[0] / NN;
    float* out = (float*)d_out;

    dim3 grid((nb + BLOCK - 1) / BLOCK);
    gae_kernel<<<grid, BLOCK>>>(x, noise, We1, be1, We2, be2, Wg1, bg1,
                                Wg2, bg2, Wd1, bd1, Wd2, bd2, out, nb);
}

// round 16
// speedup vs baseline: 1.1147x; 1.1147x over previous
#include <cuda_runtime.h>
#include <cstdint>

// R16 = R14 (best, 51.5us) with unroll tuning only: P7 unroll 4, encoder
// unroll 4, P6 fully unrolled. All arithmetic byte-identical to R14.
// Output layout: [recon (nb*8)] [lat (nb*16)] [A (nb*64)]

constexpr int NN = 8;
constexpr int BLOCK = 128;

using u64 = unsigned long long;

__device__ __forceinline__ u64 pk(float lo, float hi) {
    u64 r; asm("mov.b64 %0, {%1,%2};" : "=l"(r) : "f"(lo), "f"(hi)); return r;
}
__device__ __forceinline__ void upk(u64 v, float& lo, float& hi) {
    asm("mov.b64 {%0,%1}, %2;" : "=f"(lo), "=f"(hi) : "l"(v));
}
__device__ __forceinline__ u64 fma2(u64 a, u64 b, u64 c) {
    u64 d; asm("fma.rn.f32x2 %0, %1, %2, %3;" : "=l"(d) : "l"(a), "l"(b), "l"(c)); return d;
}
__device__ __forceinline__ u64 add2(u64 a, u64 b) {
    u64 d; asm("add.rn.f32x2 %0, %1, %2;" : "=l"(d) : "l"(a), "l"(b)); return d;
}
__device__ __forceinline__ u64 dup2(float v) { return pk(v, v); }
__device__ __forceinline__ u64 relu2(u64 v) {
    float a, b; upk(v, a, b);
    return pk(fmaxf(a, 0.0f), fmaxf(b, 0.0f));
}
__device__ __forceinline__ u64 shflx_u64(u64 v, int m) {
    float lo, hi; upk(v, lo, hi);
    lo = __shfl_xor_sync(0xffffffffu, lo, m);
    hi = __shfl_xor_sync(0xffffffffu, hi, m);
    return pk(lo, hi);
}

__device__ __forceinline__ constexpr int PIDX(int i, int j) { // i<j, 0..27
    return i * 7 - (i * (i - 1)) / 2 + (j - i - 1);
}

__global__ void __launch_bounds__(BLOCK, 7)
gae_kernel(const float* __restrict__ x, const float* __restrict__ noise,
           const float* __restrict__ We1, const float* __restrict__ be1,
           const float* __restrict__ We2, const float* __restrict__ be2,
           const float* __restrict__ Wg1, const float* __restrict__ bg1,
           const float* __restrict__ Wg2, const float* __restrict__ bg2,
           const float* __restrict__ Wd1, const float* __restrict__ bd1,
           const float* __restrict__ Wd2, const float* __restrict__ bd2,
           float* __restrict__ out, int nb)
{
    __shared__ float4 sencWq[64];       // (w1,w1, e0,e0)
    __shared__ float2 sencE1[64];       // (e1,e1)
    __shared__ float4 sencC[128];       // [k][2]: c_i = fmaf(i, w2, be1)
    __shared__ float4 sWg1q[32];        // (g0,g0, g1,g1)
    __shared__ float2 sWg1b[32];        // (bg,bg)
    __shared__ float4 sMT4[64 * 8];     // fused decoder M[e][c], c contiguous
    __shared__ float2 scw[64];          // (bg2@Wd1 + bd1, Wd2[e][1])
    __shared__ float  sbd2v;
    __shared__ float  sWg2T[32 * 33];   // Wg2 transposed, padded (staging)
    __shared__ float4 sWd1s4[32 * 16];  // Wd1 staged: [d][pp]

    const int t = threadIdx.x;
    const u64 z2 = pk(0.0f, 0.0f);

    // ---- stage raw weights ----
    if (t < 64) {
        float w1 = We1[64 + t];
        float w2 = We1[128 + t];
        float be = be1[t];
        float e0 = We2[2 * t], e1 = We2[2 * t + 1];
        sencWq[t] = make_float4(w1, w1, e0, e0);
        sencE1[t] = make_float2(e1, e1);
        float c[8];
        #pragma unroll
        for (int i = 0; i < 8; i++) c[i] = fmaf((float)i, w2, be);
        sencC[2 * t]     = make_float4(c[0], c[1], c[2], c[3]);
        sencC[2 * t + 1] = make_float4(c[4], c[5], c[6], c[7]);
    }
    if (t < 32) {
        float g0 = Wg1[t], g1 = Wg1[32 + t], bg = bg1[t];
        sWg1q[t] = make_float4(g0, g0, g1, g1);
        sWg1b[t] = make_float2(bg, bg);
    }
    for (int idx = t; idx < 1024; idx += BLOCK) {
        int c = idx >> 5, d = idx & 31;
        sWg2T[d * 33 + c] = Wg2[idx];
    }
    for (int idx = t; idx < 512; idx += BLOCK) {
        sWd1s4[idx] = *(const float4*)&Wd1[4 * idx];
    }
    if (t == 0) sbd2v = bd2[1];
    __syncthreads();

    // ---- fused decoder weights: M[e][c] = sum_d Wg2[c][d]*Wd1[d][e] ----
    {
        int c = t & 31, ep0 = t >> 5;
        u64 acc[8];
        #pragma unroll
        for (int k = 0; k < 8; k++) acc[k] = z2;
        #pragma unroll 2
        for (int d = 0; d < 32; d++) {
            u64 ad = dup2(sWg2T[d * 33 + c]);
            const ulonglong2* fb = (const ulonglong2*)&sWd1s4[d * 16 + ep0 * 4];
            ulonglong2 v0 = fb[0], v1 = fb[1], v2 = fb[2], v3 = fb[3];
            acc[0] = fma2(ad, v0.x, acc[0]);
            acc[1] = fma2(ad, v0.y, acc[1]);
            acc[2] = fma2(ad, v1.x, acc[2]);
            acc[3] = fma2(ad, v1.y, acc[3]);
            acc[4] = fma2(ad, v2.x, acc[4]);
            acc[5] = fma2(ad, v2.y, acc[5]);
            acc[6] = fma2(ad, v3.x, acc[6]);
            acc[7] = fma2(ad, v3.y, acc[7]);
        }
        #pragma unroll
        for (int k = 0; k < 8; k++) {
            int p = ep0 * 8 + k;
            float mlo, mhi; upk(acc[k], mlo, mhi);
            ((float*)sMT4)[(2 * p)     * 32 + c] = mlo;
            ((float*)sMT4)[(2 * p + 1) * 32 + c] = mhi;
        }
    }
    if (t < 64) {
        float ce = bd1[t];
        int pp = t >> 2, r = t & 3;
        #pragma unroll
        for (int d = 0; d < 32; d++) {
            float4 w = sWd1s4[d * 16 + pp];
            float vv = (r & 2) ? ((r & 1) ? w.w : w.z) : ((r & 1) ? w.y : w.x);
            ce = fmaf(bg2[d], vv, ce);
        }
        scw[t] = make_float2(ce, Wd2[t * 3 + 1]);
    }
    __syncthreads();

    const int b = blockIdx.x * BLOCK + t;
    if (b >= nb) return;

    float* out_recon = out;
    float* out_lat   = out + (size_t)nb * 8;
    float* out_A     = out + (size_t)nb * 24;

    // ---------------- P0: load x directly as 64-bit pairs ----------------
    u64 x2[4];
    {
        const ulonglong2* xp = (const ulonglong2*)(x + (size_t)b * 8);
        ulonglong2 xa = xp[0], xb = xp[1];
        x2[0] = xa.x; x2[1] = xa.y; x2[2] = xb.x; x2[3] = xb.y;
    }

    // ---------------- P1: encoder (unroll 4) ----------------
    u64 l0p[4], l1p[4];
    #pragma unroll
    for (int q = 0; q < 4; q++) { l0p[q] = z2; l1p[q] = z2; }

    #pragma unroll 4
    for (int k = 0; k < 64; k++) {
        ulonglong2 wv = *(const ulonglong2*)&sencWq[k];
        u64 w1d = wv.x, e0d = wv.y;
        u64 e1d = ((const u64*)sencE1)[k];
        const ulonglong2* cc = (const ulonglong2*)&sencC[2 * k];
        ulonglong2 c01 = cc[0], c23 = cc[1];
        u64 c2[4] = { c01.x, c01.y, c23.x, c23.y };
        #pragma unroll
        for (int q = 0; q < 4; q++) {
            u64 h = relu2(fma2(x2[q], w1d, c2[q]));
            l0p[q] = fma2(h, e0d, l0p[q]);
            l1p[q] = fma2(h, e1d, l1p[q]);
        }
    }

    // ---------------- P2/P3: stats, noise, px/py, lat store ----------------
    float px[8], py[8];
    {
        float l0[8], l1[8];
        #pragma unroll
        for (int q = 0; q < 4; q++) {
            upk(l0p[q], l0[2 * q], l0[2 * q + 1]);
            upk(l1p[q], l1[2 * q], l1[2 * q + 1]);
        }
        float mu0 = 0.0f, mu1 = 0.0f;
        #pragma unroll
        for (int i = 0; i < 8; i++) { mu0 += l0[i]; mu1 += l1[i]; }
        mu0 *= 0.125f; mu1 *= 0.125f;

        float v0 = 0.0f, v1 = 0.0f;
        #pragma unroll
        for (int i = 0; i < 8; i++) {
            float c0 = l0[i] - mu0, c1 = l1[i] - mu1;
            v0 += c0 * c0; v1 += c1 * c1;
        }
        float sc0 = 3.0f / (sqrtf(v0 * (1.0f / 7.0f)) + 1e-8f);
        float sc1 = 3.0f / (sqrtf(v1 * (1.0f / 7.0f)) + 1e-8f);

        float nz[16];
        {
            const float4* np = (const float4*)(noise + (size_t)b * 16);
            float4 q0 = np[0], q1 = np[1], q2 = np[2], q3 = np[3];
            nz[0]=q0.x; nz[1]=q0.y; nz[2]=q0.z; nz[3]=q0.w;
            nz[4]=q1.x; nz[5]=q1.y; nz[6]=q1.z; nz[7]=q1.w;
            nz[8]=q2.x; nz[9]=q2.y; nz[10]=q2.z; nz[11]=q2.w;
            nz[12]=q3.x; nz[13]=q3.y; nz[14]=q3.z; nz[15]=q3.w;
        }
        #pragma unroll
        for (int i = 0; i < 8; i++) {
            px[i] = ((l0[i] - mu0) * sc0) + nz[2 * i]     * 0.05f;
            py[i] = ((l1[i] - mu1) * sc1) + nz[2 * i + 1] * 0.05f;
        }
        float4* lp = (float4*)(out_lat + (size_t)b * 16);
        #pragma unroll
        for (int q = 0; q < 4; q++) {
            float4 o;
            o.x = px[2 * q];     o.y = py[2 * q];
            o.z = px[2 * q + 1]; o.w = py[2 * q + 1];
            lp[q] = o;
        }
    }

    // ---------------- P4: Gabriel graph (expression-identical) ----------------
    unsigned am = 0;
    int deg[8];
    #pragma unroll
    for (int i = 0; i < 8; i++) deg[i] = 1;

    #pragma unroll
    for (int i = 0; i < 8; i++) {
        #pragma unroll
        for (int j = i + 1; j < 8; j++) {
            float mx = (px[i] + px[j]) * 0.5f;
            float my = (py[i] + py[j]) * 0.5f;
            float dx = px[i] - mx, dy = py[i] - my;
            float r2 = dx * dx + dy * dy;
            float mind2 = 3.402823e38f;
            #pragma unroll
            for (int k = 0; k < 8; k++) {
                if (k != i && k != j) {
                    float ax = px[k] - mx, ay = py[k] - my;
                    mind2 = fminf(mind2, ax * ax + ay * ay);
                }
            }
            if (mind2 >= r2) {
                am |= (1u << PIDX(i, j));
                deg[i]++; deg[j]++;
            }
        }
    }

    float dinv[8];
    #pragma unroll
    for (int i = 0; i < 8; i++) dinv[i] = rsqrtf((float)deg[i]);

    // ---------------- A output: warp-coalesced via bitmask shuffle ----------
    {
        const int lane = t & 31;
        const int m_  = lane & 15;
        const int ai_ = m_ >> 1;
        const int jb  = (m_ & 1) * 4;
        int sh[4];
        #pragma unroll
        for (int jj = 0; jj < 4; jj++) {
            int j = jb + jj;
            if (j == ai_) sh[jj] = 31;
            else {
                int lo = ai_ < j ? ai_ : j;
                int hi = ai_ < j ? j : ai_;
                sh[jj] = lo * 7 - (lo * (lo - 1)) / 2 + (hi - lo - 1);
            }
        }
        float4* warpA = (float4*)(out_A + (size_t)(blockIdx.x * BLOCK + (t & ~31)) * 64);
        #pragma unroll
        for (int k = 0; k < 16; k++) {
            unsigned a = __shfl_sync(0xffffffffu, am, 2 * k + (lane >> 4));
            float4 o;
            o.x = ((a >> sh[0]) & 1u) ? 1.0f : 0.0f;
            o.y = ((a >> sh[1]) & 1u) ? 1.0f : 0.0f;
            o.z = ((a >> sh[2]) & 1u) ? 1.0f : 0.0f;
            o.w = ((a >> sh[3]) & 1u) ? 1.0f : 0.0f;
            warpA[k * 32 + lane] = o;
        }
    }

    // ---------------- P5: qx/qy/s via wx = dinv*px (predicated adds) --------
    u64 qx2[4], qy2[4], s2[4];
    {
        float wx[8], wy[8];
        #pragma unroll
        for (int j = 0; j < 8; j++) {
            wx[j] = dinv[j] * px[j];
            wy[j] = dinv[j] * py[j];
        }

        float tqx = 0.0f, tqy = 0.0f, ts = 0.0f;
        #pragma unroll
        for (int n = 0; n < 8; n++) {
            float tx = wx[n], ty = wy[n], td = dinv[n];
            #pragma unroll
            for (int j = 0; j < 8; j++) {
                if (j == n) continue;
                int p = (n < j) ? PIDX(n, j) : PIDX(j, n);
                bool adj = (am >> p) & 1u;
                if (adj) { tx += wx[j]; ty += wy[j]; td += dinv[j]; }
            }
            float qxn = dinv[n] * tx;
            float qyn = dinv[n] * ty;
            float sn  = dinv[n] * td * 0.125f;
            if (n & 1) {
                qx2[n >> 1] = pk(tqx, qxn);
                qy2[n >> 1] = pk(tqy, qyn);
                s2[n >> 1]  = pk(ts, sn);
            } else {
                tqx = qxn; tqy = qyn; ts = sn;
            }
        }
    }

    // ---------------- P6: GCN channel values u_c (full unroll) --------------
    u64 u2[16];
    {
        float tu = 0.0f;
        #pragma unroll
        for (int c = 0; c < 32; c++) {
            ulonglong2 gv = *(const ulonglong2*)&sWg1q[c];
            u64 g0d = gv.x, g1d = gv.y;
            u64 bgd = ((const u64*)sWg1b)[c];
            u64 acc2 = z2;
            #pragma unroll
            for (int q = 0; q < 4; q++) {
                u64 a = fma2(qx2[q], g0d, fma2(qy2[q], g1d, bgd));
                acc2 = fma2(s2[q], relu2(a), acc2);
            }
            float ua, ub; upk(acc2, ua, ub);
            float uc = ua + ub;
            if (c & 1) u2[c >> 1] = pk(tu, uc);
            else       tu = uc;
        }
    }

    // ---------------- P7: pair-split decoder, unroll 4 ----------------------
    float recon = sbd2v;
    {
        const int lane = t & 31;
        const bool lowq = (lane & 16) == 0;
        const int rot = (t >> 5) << 4;               // 0,16,32,48 per warp

        u64 uo[8], up_[8];
        #pragma unroll
        for (int k = 0; k < 8; k++) {
            uo[k]   = lowq ? u2[k]     : u2[k + 8];
            u64 snd = lowq ? u2[k + 8] : u2[k];
            up_[k]  = shflx_u64(snd, 16);
        }

        const int colbase = lowq ? 0 : 4;
        #pragma unroll 4
        for (int ee = 0; ee < 64; ee++) {
            int e = (ee + rot) & 63;
            const ulonglong2* wr2 = (const ulonglong2*)&sMT4[e * 8 + colbase];
            ulonglong2 v0 = wr2[0], v1 = wr2[1], v2 = wr2[2], v3 = wr2[3];
            u64 m0 = v0.x, m1 = v0.y, m2 = v1.x, m3 = v1.y;
            u64 m4 = v2.x, m5 = v2.y, m6 = v3.x, m7 = v3.y;

            u64 aA = fma2(uo[0], m0, z2); u64 aB = fma2(uo[1], m1, z2);
            aA = fma2(uo[2], m2, aA);     aB = fma2(uo[3], m3, aB);
            aA = fma2(uo[4], m4, aA);     aB = fma2(uo[5], m5, aB);
            aA = fma2(uo[6], m6, aA);     aB = fma2(uo[7], m7, aB);
            u64 ao = add2(aA, aB);
            float oa, ob; upk(ao, oa, ob);
            float p_own = oa + ob;

            u64 bA = fma2(up_[0], m0, z2); u64 bB = fma2(up_[1], m1, z2);
            bA = fma2(up_[2], m2, bA);     bB = fma2(up_[3], m3, bB);
            bA = fma2(up_[4], m4, bA);     bB = fma2(up_[5], m5, bB);
            bA = fma2(up_[6], m6, bA);     bB = fma2(up_[7], m7, bB);
            u64 bo = add2(bA, bB);
            float pa, pb; upk(bo, pa, pb);
            float p_oth = pa + pb;

            float p_rcv = __shfl_xor_sync(0xffffffffu, p_oth, 16);

            float2 cw = scw[e];
            float pre = (p_own + p_rcv) + cw.x;
            recon = fmaf(fmaxf(pre, 0.0f), cw.y, recon);
        }
    }

    {
        float4 r4 = {recon, recon, recon, recon};
        float4* rp = (float4*)(out_recon + (size_t)b * 8);
        rp[0] = r4;
        rp[1] = r4;
    }
}

extern "C" void kernel_launch(void* const* d_in, const int* in_sizes, int n_in,
                              void* d_out, int out_size)
{
    const float* x     = (const float*)d_in[0];
    const float* noise = (const float*)d_in[1];
    const float* We1   = (const float*)d_in[2];
    const float* be1   = (const float*)d_in[3];
    const float* We2   = (const float*)d_in[4];
    const float* be2   = (const float*)d_in[5];
    const float* Wg1   = (const float*)d_in[6];
    const float* bg1   = (const float*)d_in[7];
    const float* Wg2   = (const float*)d_in[8];
    const float* bg2   = (const float*)d_in[9];
    const float* Wd1   = (const float*)d_in[10];
    const float* bd1   = (const float*)d_in[11];
    const float* Wd2   = (const float*)d_in[12];
    const float* bd2   = (const float*)d_in[13];

    const int nb = in_sizes[0] / NN;
    float* out = (float*)d_out;

    dim3 grid((nb + BLOCK - 1) / BLOCK);
    gae_kernel<<<grid, BLOCK>>>(x, noise, We1, be1, We2, be2, Wg1, bg1,
                                Wg2, bg2, Wd1, bd1, Wd2, bd2, out, nb);
}